// round 14
// baseline (speedup 1.0000x reference)
#include <cuda_runtime.h>
#include <cuda_fp16.h>
#include <math.h>

#define BATCH 16
#define DK    512
#define NN    2048
#define MM    2048

#define BMT 128             // N rows per block
#define BNT 128             // M cols per tile
#define BK  64              // K per stage (4 x m16n8k16)
#define LDK 72              // halves per row (64 + 8 pad)
#define NKT (DK / BK)       // 8
#define MSPLIT 8            // m-tile groups (blocks) per n-tile
#define NMT_LOC (MM / BNT / MSPLIT)   // 2 m-tiles per block
#define VLD 136             // Vh row stride in halves
#define THREADS 256

// halves
#define SM_AH   (2 * BMT * LDK)        // 18432
#define SM_BH   (2 * BNT * LDK)        // 18432
#define SM_VH   (16 * VLD)             // 2176 per buffer
// floats
#define SM_PV   (2 * BMT * 9)
#define SM_TOTAL_BYTES ((SM_AH + SM_BH + 2 * SM_VH) * 2 + SM_PV * 4)  // 91648

__device__ __half g_a16[(size_t)BATCH * NN * DK];   // [b][n][d]
__device__ __half g_b16[(size_t)BATCH * MM * DK];   // [b][m][d]
__device__ __half g_v16[(size_t)BATCH * 16 * MM];   // [b][16][m]
__device__ float  g_pv[(size_t)BATCH * MSPLIT * 6 * NN];  // unnormalized partials

__device__ __forceinline__ unsigned smem_u32(const void* p) {
    unsigned a;
    asm("{ .reg .u64 t; cvta.to.shared.u64 t, %1; cvt.u32.u64 %0, t; }" : "=r"(a) : "l"(p));
    return a;
}
__device__ __forceinline__ void cp_async16(void* smem, const void* gmem) {
    unsigned s = (unsigned)__cvta_generic_to_shared(smem);
    asm volatile("cp.async.cg.shared.global [%0], [%1], 16;\n" :: "r"(s), "l"(gmem));
}
__device__ __forceinline__ void cp_commit() { asm volatile("cp.async.commit_group;\n"); }
__device__ __forceinline__ void cp_wait0()  { asm volatile("cp.async.wait_group 0;\n"); }

__device__ __forceinline__ void ldsm_x4(unsigned& r0, unsigned& r1, unsigned& r2,
                                        unsigned& r3, unsigned addr) {
    asm volatile("ldmatrix.sync.aligned.m8n8.x4.shared.b16 {%0,%1,%2,%3}, [%4];"
                 : "=r"(r0), "=r"(r1), "=r"(r2), "=r"(r3) : "r"(addr));
}

// ============== pre-pass: transpose [b][d][x] fp32 -> [b][x][d] fp16 =======
__global__ __launch_bounds__(256)
void conv_transpose(const float* __restrict__ in, __half* __restrict__ out) {
    __shared__ float t[32][33];
    const int b  = blockIdx.z;
    const int d0 = blockIdx.y * 32;
    const int x0 = blockIdx.x * 32;
    const int tx = threadIdx.x & 31;
    const int ty = threadIdx.x >> 5;

    const float* src = in + (size_t)b * DK * NN + (size_t)d0 * NN + x0;
    #pragma unroll
    for (int i = 0; i < 4; ++i)
        t[ty + i * 8][tx] = src[(size_t)(ty + i * 8) * NN + tx];
    __syncthreads();

    __half* dst = out + (size_t)b * NN * DK + (size_t)x0 * DK + d0;
    #pragma unroll
    for (int i = 0; i < 4; ++i)
        dst[(size_t)(ty + i * 8) * DK + tx] = __float2half_rn(t[tx][ty + i * 8]);
}

// ============== pre-pass: pack V rows (high + residual) ====================
__global__ __launch_bounds__(256)
void prep_v(const float* __restrict__ tgt, const float* __restrict__ tdm,
            const float* __restrict__ tim) {
    const int b = blockIdx.y;
    const int m = blockIdx.x * 256 + threadIdx.x;
    const float* t0 = tgt + (size_t)b * 3 * MM;
    __half* dst = g_v16 + (size_t)b * 16 * MM;
    float v[5];
    v[0] = t0[m];
    v[1] = t0[MM + m];
    v[2] = t0[2 * MM + m];
    v[3] = tdm[(size_t)b * MM + m];
    v[4] = tim[(size_t)b * MM + m];
    #pragma unroll
    for (int j = 0; j < 5; ++j) {
        __half h = __float2half_rn(v[j]);
        dst[j * MM + m] = h;
        dst[(8 + j) * MM + m] = __float2half_rn(v[j] - __half2float(h));
    }
    const __half z = __float2half_rn(0.f);
    dst[5 * MM + m] = __float2half_rn(1.f);
    dst[6 * MM + m] = z;  dst[7 * MM + m] = z;
    dst[13 * MM + m] = z; dst[14 * MM + m] = z; dst[15 * MM + m] = z;
}

// ========= fused: scores GEMM(fp16, ldmatrix) + exp2 + compensated PV-MMA ==
// 8 warps: warp grid 4(m) x 2(n), warp tile 32 rows x 64 cols.
__global__ __launch_bounds__(THREADS, 2)
void fused_attn() {
    extern __shared__ char smraw[];
    __half* As = (__half*)smraw;                       // [2*BMT][LDK]
    __half* Bs = As + SM_AH;                           // [2*BNT][LDK]
    __half* Vh = Bs + SM_BH;                           // 2 buffers [16][VLD]
    float*  Pv = (float*)(Vh + 2 * SM_VH);             // [2][128][9]

    const int nt = blockIdx.x;
    const int mh = blockIdx.y;
    const int b  = blockIdx.z;
    const int n0 = nt * BMT;
    const int mbase = mh * NMT_LOC * BNT;

    const __half* Ab = g_a16 + (size_t)b * NN * DK;
    const __half* Bb = g_b16 + (size_t)b * MM * DK;
    const __half* Vb = g_v16 + (size_t)b * 16 * MM;

    const int tid  = threadIdx.x;
    const int lane = tid & 31;
    const int warp = tid >> 5;       // 0..7
    const int wm = warp & 3;         // 0..3 -> 32 rows each
    const int wn = warp >> 2;        // 0..1 -> 64 cols each
    const int g  = lane >> 2;        // 0..7
    const int tq = lane & 3;         // 0..3

    // ldmatrix per-lane offsets (in halves).
    const int q = lane >> 3;
    const int a_off = ((lane & 7) + ((q & 1) << 3)) * LDK + ((q >> 1) << 3);
    const int b_off = ((lane & 7) + ((q >> 1) << 3)) * LDK + ((q & 1) << 3);
    const unsigned As_u = smem_u32(As);
    const unsigned Bs_u = smem_u32(Bs);

    float pvH[2][4], pvR[2][4];
    #pragma unroll
    for (int i = 0; i < 2; ++i)
        #pragma unroll
        for (int c = 0; c < 4; ++c) { pvH[i][c] = 0.f; pvR[i][c] = 0.f; }

    auto issue_stage = [&](int m0, int kt, int s) {
        const int k0 = kt * BK;
        #pragma unroll
        for (int i = 0; i < 4; ++i) {
            const int idx = tid + i * THREADS;    // 0..1023
            const int r = idx >> 3;               // row 0..127
            const int cs = (idx & 7) * 8;         // half offset 0..56
            cp_async16(&As[(s * BMT + r) * LDK + cs], &Ab[(size_t)(n0 + r) * DK + k0 + cs]);
            cp_async16(&Bs[(s * BNT + r) * LDK + cs], &Bb[(size_t)(m0 + r) * DK + k0 + cs]);
        }
    };
    auto issue_V = [&](int m0, int vbuf) {
        __half* Vd = Vh + vbuf * SM_VH;
        const int j = tid >> 4;               // row 0..15
        const int c = (tid & 15) * 8;         // 0..120
        cp_async16(&Vd[j * VLD + c], &Vb[(size_t)j * MM + m0 + c]);
    };

    issue_stage(mbase, 0, 0);
    issue_V(mbase, 0);
    cp_commit();

    // exp(x/sqrt(512)) = exp2(x * log2(e)/sqrt(512))
    const float scale2 = 0.063763115930097f;   // log2(e)/sqrt(512)

    for (int mt = 0; mt < NMT_LOC; ++mt) {
        const int m0 = mbase + mt * BNT;

        float acc[2][8][4];
        #pragma unroll
        for (int i = 0; i < 2; ++i)
            #pragma unroll
            for (int j = 0; j < 8; ++j)
                #pragma unroll
                for (int c = 0; c < 4; ++c) acc[i][j][c] = 0.f;

        // -------- S = A·B^T  (128x128 tile over K=512, BK=64 stages) --------
        for (int kt = 0; kt < NKT; ++kt) {
            cp_wait0();
            __syncthreads();   // stage kt arrived AND all warps done with kt-1
            if (kt + 1 < NKT) { issue_stage(m0, kt + 1, (kt + 1) & 1); cp_commit(); }

            const int s = kt & 1;
            #pragma unroll
            for (int ks = 0; ks < 4; ++ks) {
                const int kbase = ks * 16;
                unsigned afr[2][4], bfr[8][2];
                #pragma unroll
                for (int mi = 0; mi < 2; ++mi) {
                    const unsigned aaddr = As_u + 2u *
                        (unsigned)((s * BMT + wm * 32 + mi * 16) * LDK + kbase + a_off);
                    ldsm_x4(afr[mi][0], afr[mi][1], afr[mi][2], afr[mi][3], aaddr);
                }
                #pragma unroll
                for (int nip = 0; nip < 4; ++nip) {
                    const unsigned baddr = Bs_u + 2u *
                        (unsigned)((s * BNT + wn * 64 + nip * 16) * LDK + kbase + b_off);
                    ldsm_x4(bfr[2 * nip][0], bfr[2 * nip][1],
                            bfr[2 * nip + 1][0], bfr[2 * nip + 1][1], baddr);
                }
                #pragma unroll
                for (int mi = 0; mi < 2; ++mi)
                    #pragma unroll
                    for (int ni = 0; ni < 8; ++ni) {
                        asm volatile(
                            "mma.sync.aligned.m16n8k16.row.col.f32.f16.f16.f32 "
                            "{%0,%1,%2,%3}, {%4,%5,%6,%7}, {%8,%9}, {%0,%1,%2,%3};"
                            : "+f"(acc[mi][ni][0]), "+f"(acc[mi][ni][1]),
                              "+f"(acc[mi][ni][2]), "+f"(acc[mi][ni][3])
                            : "r"(afr[mi][0]), "r"(afr[mi][1]),
                              "r"(afr[mi][2]), "r"(afr[mi][3]),
                              "r"(bfr[ni][0]), "r"(bfr[ni][1]));
                    }
            }
            // no end barrier: next stage's top barrier provides the WAR guard
        }

        // overlap next tile's first stage + V with the exp/PV phase
        if (mt + 1 < NMT_LOC) {
            issue_stage(m0 + BNT, 0, 0);
            issue_V(m0 + BNT, (mt + 1) & 1);
            cp_commit();
        }

        // -------- E = exp2(scale2*S) in registers --------
        #pragma unroll
        for (int mi = 0; mi < 2; ++mi)
            #pragma unroll
            for (int ni = 0; ni < 8; ++ni)
                #pragma unroll
                for (int c = 0; c < 4; ++c)
                    acc[mi][ni][c] = exp2f(acc[mi][ni][c] * scale2);

        // -------- compensated PV += E · V^T (this warp's 64 score cols) ----
        const __half* Vc = Vh + (mt & 1) * SM_VH;
        #pragma unroll
        for (int kk = 0; kk < 4; ++kk) {
            const int koff = wn * 64 + kk * 16;
            unsigned vh0 = *(const unsigned*)(Vc + g * VLD + koff + 2 * tq);
            unsigned vh1 = *(const unsigned*)(Vc + g * VLD + koff + 2 * tq + 8);
            unsigned vr0 = *(const unsigned*)(Vc + (8 + g) * VLD + koff + 2 * tq);
            unsigned vr1 = *(const unsigned*)(Vc + (8 + g) * VLD + koff + 2 * tq + 8);
            #pragma unroll
            for (int mi = 0; mi < 2; ++mi) {
                __half2 eh[4], er[4];
                #pragma unroll
                for (int p = 0; p < 2; ++p) {
                    const float e0 = acc[mi][2 * kk + p][0];
                    const float e1 = acc[mi][2 * kk + p][1];
                    const float e2 = acc[mi][2 * kk + p][2];
                    const float e3 = acc[mi][2 * kk + p][3];
                    __half2 h01 = __floats2half2_rn(e0, e1);
                    __half2 h23 = __floats2half2_rn(e2, e3);
                    float2 f01 = __half22float2(h01);
                    float2 f23 = __half22float2(h23);
                    eh[2 * p]     = h01;
                    eh[2 * p + 1] = h23;
                    er[2 * p]     = __floats2half2_rn(e0 - f01.x, e1 - f01.y);
                    er[2 * p + 1] = __floats2half2_rn(e2 - f23.x, e3 - f23.y);
                }
                asm volatile(
                    "mma.sync.aligned.m16n8k16.row.col.f32.f16.f16.f32 "
                    "{%0,%1,%2,%3}, {%4,%5,%6,%7}, {%8,%9}, {%0,%1,%2,%3};"
                    : "+f"(pvH[mi][0]), "+f"(pvH[mi][1]),
                      "+f"(pvH[mi][2]), "+f"(pvH[mi][3])
                    : "r"(*(unsigned*)&eh[0]), "r"(*(unsigned*)&eh[1]),
                      "r"(*(unsigned*)&eh[2]), "r"(*(unsigned*)&eh[3]),
                      "r"(vh0), "r"(vh1));
                asm volatile(
                    "mma.sync.aligned.m16n8k16.row.col.f32.f16.f16.f32 "
                    "{%0,%1,%2,%3}, {%4,%5,%6,%7}, {%8,%9}, {%0,%1,%2,%3};"
                    : "+f"(pvH[mi][0]), "+f"(pvH[mi][1]),
                      "+f"(pvH[mi][2]), "+f"(pvH[mi][3])
                    : "r"(*(unsigned*)&er[0]), "r"(*(unsigned*)&er[1]),
                      "r"(*(unsigned*)&er[2]), "r"(*(unsigned*)&er[3]),
                      "r"(vh0), "r"(vh1));
                asm volatile(
                    "mma.sync.aligned.m16n8k16.row.col.f32.f16.f16.f32 "
                    "{%0,%1,%2,%3}, {%4,%5,%6,%7}, {%8,%9}, {%0,%1,%2,%3};"
                    : "+f"(pvR[mi][0]), "+f"(pvR[mi][1]),
                      "+f"(pvR[mi][2]), "+f"(pvR[mi][3])
                    : "r"(*(unsigned*)&eh[0]), "r"(*(unsigned*)&eh[1]),
                      "r"(*(unsigned*)&eh[2]), "r"(*(unsigned*)&eh[3]),
                      "r"(vr0), "r"(vr1));
            }
        }
    }

    // -------- cross-warp PV merge (wn=0 stores, wn=1 adds) --------
    float* PvH = Pv;
    float* PvR = Pv + BMT * 9;
    __syncthreads();
    if (wn == 0) {
        #pragma unroll
        for (int mi = 0; mi < 2; ++mi) {
            const int r = wm * 32 + mi * 16 + g;
            PvH[r * 9 + 2 * tq]           = pvH[mi][0];
            PvH[r * 9 + 2 * tq + 1]       = pvH[mi][1];
            PvH[(r + 8) * 9 + 2 * tq]     = pvH[mi][2];
            PvH[(r + 8) * 9 + 2 * tq + 1] = pvH[mi][3];
            PvR[r * 9 + 2 * tq]           = pvR[mi][0];
            PvR[r * 9 + 2 * tq + 1]       = pvR[mi][1];
            PvR[(r + 8) * 9 + 2 * tq]     = pvR[mi][2];
            PvR[(r + 8) * 9 + 2 * tq + 1] = pvR[mi][3];
        }
    }
    __syncthreads();
    if (wn == 1) {
        #pragma unroll
        for (int mi = 0; mi < 2; ++mi) {
            const int r = wm * 32 + mi * 16 + g;
            PvH[r * 9 + 2 * tq]           += pvH[mi][0];
            PvH[r * 9 + 2 * tq + 1]       += pvH[mi][1];
            PvH[(r + 8) * 9 + 2 * tq]     += pvH[mi][2];
            PvH[(r + 8) * 9 + 2 * tq + 1] += pvH[mi][3];
            PvR[r * 9 + 2 * tq]           += pvR[mi][0];
            PvR[r * 9 + 2 * tq + 1]       += pvR[mi][1];
            PvR[(r + 8) * 9 + 2 * tq]     += pvR[mi][2];
            PvR[(r + 8) * 9 + 2 * tq + 1] += pvR[mi][3];
        }
    }
    __syncthreads();

    // -------- write unnormalized partial (rows 0-4 = pv, row 5 = l) --------
    if (tid < BMT) {
        float* out = g_pv + (((size_t)b * MSPLIT + mh) * 6) * NN + n0 + tid;
        #pragma unroll
        for (int j = 0; j < 6; ++j)
            out[j * NN] = PvH[tid * 9 + j] + PvR[tid * 9 + j];
    }
}

// ======================= reductions =========================================
__device__ __forceinline__ float warp_sum(float v) {
    #pragma unroll
    for (int o = 16; o; o >>= 1) v += __shfl_down_sync(0xffffffffu, v, o);
    return v;
}
__device__ __forceinline__ float warp_max(float v) {
    #pragma unroll
    for (int o = 16; o; o >>= 1) v = fmaxf(v, __shfl_down_sync(0xffffffffu, v, o));
    return v;
}
__device__ __forceinline__ float warp_min(float v) {
    #pragma unroll
    for (int o = 16; o; o >>= 1) v = fminf(v, __shfl_down_sync(0xffffffffu, v, o));
    return v;
}

// ======================= finalize: merge partials, mask, H, SVD, R,t =======
__device__ __forceinline__ float sigm(float x) { return 1.f / (1.f + __expf(-x)); }

__global__ __launch_bounds__(256)
void finalize_kernel(const float* __restrict__ src,
                     const float* __restrict__ sdm,
                     const float* __restrict__ sim,
                     float* __restrict__ out) {
    __shared__ float scorr[5 * NN];
    __shared__ float part[8][9];
    __shared__ float bc[20];

    const int b = blockIdx.x;
    const int tid  = threadIdx.x;
    const int lane = tid & 31;
    const int w    = tid >> 5;

    const float* S  = src + (size_t)b * 3 * NN;
    const float* Dm = sdm + (size_t)b * NN;
    const float* Im = sim + (size_t)b * NN;
    const float* P  = g_pv + ((size_t)b * MSPLIT * 6) * NN;

    for (int n = tid; n < NN; n += 256) {
        float s[6];
        #pragma unroll
        for (int j = 0; j < 6; ++j) {
            float acc = 0.f;
            #pragma unroll
            for (int mh = 0; mh < MSPLIT; ++mh)
                acc += P[((size_t)mh * 6 + j) * NN + n];
            s[j] = acc;
        }
        const float inv = 1.f / s[5];
        #pragma unroll
        for (int j = 0; j < 5; ++j) scorr[j * NN + n] = s[j] * inv;
    }
    __syncthreads();

    float a[8] = {0, 0, 0, 0, 0, 0, INFINITY, -INFINITY};
    for (int n = tid; n < NN; n += 256) {
        a[0] += S[n]; a[1] += S[NN + n]; a[2] += S[2 * NN + n];
        a[3] += scorr[n]; a[4] += scorr[NN + n]; a[5] += scorr[2 * NN + n];
        float dep = 0.5f * (Dm[n] + scorr[3 * NN + n]);
        float img = 0.5f * (Im[n] + scorr[4 * NN + n]);
        float mk = sigm(dep) * sigm(img);
        a[6] = fminf(a[6], mk);
        a[7] = fmaxf(a[7], mk);
    }
    #pragma unroll
    for (int j = 0; j < 6; ++j) a[j] = warp_sum(a[j]);
    a[6] = warp_min(a[6]);
    a[7] = warp_max(a[7]);
    if (lane == 0)
        #pragma unroll
        for (int j = 0; j < 8; ++j) part[w][j] = a[j];
    __syncthreads();
    if (tid < 8) {
        float r = part[0][tid];
        if (tid < 6)      { for (int i = 1; i < 8; ++i) r += part[i][tid];        r *= (1.f / NN); }
        else if (tid == 6){ for (int i = 1; i < 8; ++i) r = fminf(r, part[i][6]); }
        else              { for (int i = 1; i < 8; ++i) r = fmaxf(r, part[i][7]); }
        bc[tid] = r;
    }
    __syncthreads();
    const float sm0 = bc[0], sm1 = bc[1], sm2 = bc[2];
    const float cm0 = bc[3], cm1 = bc[4], cm2 = bc[5];
    const float MN = bc[6], MX = bc[7];
    const float invden = 1.f / fmaxf(MX - MN, 1e-6f);

    float h[9];
    #pragma unroll
    for (int i = 0; i < 9; ++i) h[i] = 0.f;
    for (int n = tid; n < NN; n += 256) {
        float dep = 0.5f * (Dm[n] + scorr[3 * NN + n]);
        float img = 0.5f * (Im[n] + scorr[4 * NN + n]);
        float wt = (sigm(dep) * sigm(img) - MN) * invden;
        float x0 = S[n] - sm0, x1 = S[NN + n] - sm1, x2 = S[2 * NN + n] - sm2;
        float y0 = scorr[n] - cm0, y1 = scorr[NN + n] - cm1, y2 = scorr[2 * NN + n] - cm2;
        h[0] += wt * x0 * y0; h[1] += wt * x0 * y1; h[2] += wt * x0 * y2;
        h[3] += wt * x1 * y0; h[4] += wt * x1 * y1; h[5] += wt * x1 * y2;
        h[6] += wt * x2 * y0; h[7] += wt * x2 * y1; h[8] += wt * x2 * y2;
    }
    #pragma unroll
    for (int i = 0; i < 9; ++i) h[i] = warp_sum(h[i]);
    __syncthreads();
    if (lane == 0)
        #pragma unroll
        for (int i = 0; i < 9; ++i) part[w][i] = h[i];
    __syncthreads();
    if (tid < 9) {
        float r = part[0][tid];
        for (int i = 1; i < 8; ++i) r += part[i][tid];
        bc[8 + tid] = r;
    }
    __syncthreads();

    if (tid == 0) {
        double Hd[3][3];
        for (int i = 0; i < 3; ++i)
            for (int j = 0; j < 3; ++j) Hd[i][j] = (double)bc[8 + i * 3 + j];

        double A[3][3];
        for (int i = 0; i < 3; ++i)
            for (int j = 0; j < 3; ++j) {
                double s = 0;
                for (int k = 0; k < 3; ++k) s += Hd[k][i] * Hd[k][j];
                A[i][j] = s;
            }
        double V[3][3] = {{1, 0, 0}, {0, 1, 0}, {0, 0, 1}};
        const int pr[3] = {0, 0, 1}, qr[3] = {1, 2, 2};
        for (int sweep = 0; sweep < 8; ++sweep) {
            for (int pi = 0; pi < 3; ++pi) {
                const int p = pr[pi], q = qr[pi];
                double apq = A[p][q];
                if (fabs(apq) < 1e-300) continue;
                double theta = (A[q][q] - A[p][p]) / (2.0 * apq);
                double t = ((theta >= 0.0) ? 1.0 : -1.0) /
                           (fabs(theta) + sqrt(1.0 + theta * theta));
                double cth = 1.0 / sqrt(1.0 + t * t);
                double sth = t * cth;
                for (int k = 0; k < 3; ++k) {
                    double akp = A[k][p], akq = A[k][q];
                    A[k][p] = cth * akp - sth * akq;
                    A[k][q] = sth * akp + cth * akq;
                }
                for (int k = 0; k < 3; ++k) {
                    double apk = A[p][k], aqk = A[q][k];
                    A[p][k] = cth * apk - sth * aqk;
                    A[q][k] = sth * apk + cth * aqk;
                }
                for (int k = 0; k < 3; ++k) {
                    double vkp = V[k][p], vkq = V[k][q];
                    V[k][p] = cth * vkp - sth * vkq;
                    V[k][q] = sth * vkp + cth * vkq;
                }
            }
        }
        double w3[3] = {A[0][0], A[1][1], A[2][2]};
        for (int i = 0; i < 2; ++i)
            for (int j = i + 1; j < 3; ++j)
                if (w3[j] > w3[i]) {
                    double tw = w3[i]; w3[i] = w3[j]; w3[j] = tw;
                    for (int k = 0; k < 3; ++k) {
                        double tv = V[k][i]; V[k][i] = V[k][j]; V[k][j] = tv;
                    }
                }
        double U[3][3];
        for (int j = 0; j < 3; ++j) {
            double sig = sqrt(w3[j] > 0.0 ? w3[j] : 0.0);
            double inv = 1.0 / (sig > 1e-30 ? sig : 1e-30);
            for (int i = 0; i < 3; ++i)
                U[i][j] = (Hd[i][0] * V[0][j] + Hd[i][1] * V[1][j] + Hd[i][2] * V[2][j]) * inv;
        }
        double R[3][3];
        for (int i = 0; i < 3; ++i)
            for (int j = 0; j < 3; ++j)
                R[i][j] = V[i][0] * U[j][0] + V[i][1] * U[j][1] + V[i][2] * U[j][2];
        double det = R[0][0] * (R[1][1] * R[2][2] - R[1][2] * R[2][1])
                   - R[0][1] * (R[1][0] * R[2][2] - R[1][2] * R[2][0])
                   + R[0][2] * (R[1][0] * R[2][1] - R[1][1] * R[2][0]);
        if (det < 0.0) {
            for (int k = 0; k < 3; ++k) V[k][2] = -V[k][2];
            for (int i = 0; i < 3; ++i)
                for (int j = 0; j < 3; ++j)
                    R[i][j] = V[i][0] * U[j][0] + V[i][1] * U[j][1] + V[i][2] * U[j][2];
        }
        const double smv[3] = {sm0, sm1, sm2};
        const double cmv[3] = {cm0, cm1, cm2};

        float* Rout = out + b * 9;
        float* tout = out + BATCH * 9 + b * 3;
        for (int i = 0; i < 3; ++i) {
            for (int j = 0; j < 3; ++j) Rout[i * 3 + j] = (float)R[i][j];
            double ti = -(R[i][0] * smv[0] + R[i][1] * smv[1] + R[i][2] * smv[2]) + cmv[i];
            tout[i] = (float)ti;
        }
    }
}

// ======================= launch ============================================
extern "C" void kernel_launch(void* const* d_in, const int* in_sizes, int n_in,
                              void* d_out, int out_size) {
    const float* src_emb = (const float*)d_in[0];
    const float* tgt_emb = (const float*)d_in[1];
    const float* src     = (const float*)d_in[2];
    const float* tgt     = (const float*)d_in[3];
    const float* sdm     = (const float*)d_in[4];
    const float* tdm     = (const float*)d_in[5];
    const float* sim     = (const float*)d_in[6];
    const float* tim     = (const float*)d_in[7];
    float* out = (float*)d_out;

    __half* a16;  cudaGetSymbolAddress((void**)&a16, g_a16);
    __half* b16;  cudaGetSymbolAddress((void**)&b16, g_b16);

    cudaFuncSetAttribute(fused_attn, cudaFuncAttributeMaxDynamicSharedMemorySize,
                         SM_TOTAL_BYTES);

    dim3 gc(NN / 32, DK / 32, BATCH);
    conv_transpose<<<gc, 256>>>(src_emb, a16);
    conv_transpose<<<gc, 256>>>(tgt_emb, b16);
    dim3 gv(MM / 256, BATCH);
    prep_v<<<gv, 256>>>(tgt, tdm, tim);

    dim3 grid(NN / BMT, MSPLIT, BATCH);   // 16 x 8 x 16 = 2048 blocks
    fused_attn<<<grid, THREADS, SM_TOTAL_BYTES>>>();
    finalize_kernel<<<BATCH, 256>>>(src, sdm, sim, out);
}

// round 15
// speedup vs baseline: 1.0374x; 1.0374x over previous
#include <cuda_runtime.h>
#include <cuda_fp16.h>
#include <math.h>

#define BATCH 16
#define DK    512
#define NN    2048
#define MM    2048

#define BMT 128             // N rows per block
#define BNT 128             // M cols per tile
#define BK  64              // K per stage (4 x m16n8k16)
#define LDK 72              // halves per row (64 + 8 pad)
#define NKT (DK / BK)       // 8
#define MSPLIT 4            // m-tile groups (blocks) per n-tile
#define NMT_LOC (MM / BNT / MSPLIT)   // 4 m-tiles per block
#define VLD 136             // Vh row stride in halves
#define THREADS 256

// halves
#define SM_AH   (2 * BMT * LDK)        // 18432
#define SM_BH   (2 * BNT * LDK)        // 18432
#define SM_VH   (16 * VLD)             // 2176 per buffer
// floats
#define SM_PV   (2 * BMT * 9)
#define SM_TOTAL_BYTES ((SM_AH + SM_BH + 2 * SM_VH) * 2 + SM_PV * 4)  // 91648

__device__ __half g_a16[(size_t)BATCH * NN * DK];   // [b][n][d]
__device__ __half g_b16[(size_t)BATCH * MM * DK];   // [b][m][d]
__device__ __half g_v16[(size_t)BATCH * 16 * MM];   // [b][16][m]
__device__ float  g_pv[(size_t)BATCH * MSPLIT * 6 * NN];  // unnormalized partials

__device__ __forceinline__ unsigned smem_u32(const void* p) {
    unsigned a;
    asm("{ .reg .u64 t; cvta.to.shared.u64 t, %1; cvt.u32.u64 %0, t; }" : "=r"(a) : "l"(p));
    return a;
}
__device__ __forceinline__ void cp_async16(void* smem, const void* gmem) {
    unsigned s = (unsigned)__cvta_generic_to_shared(smem);
    asm volatile("cp.async.cg.shared.global [%0], [%1], 16;\n" :: "r"(s), "l"(gmem));
}
__device__ __forceinline__ void cp_commit() { asm volatile("cp.async.commit_group;\n"); }
__device__ __forceinline__ void cp_wait0()  { asm volatile("cp.async.wait_group 0;\n"); }

__device__ __forceinline__ void ldsm_x4(unsigned& r0, unsigned& r1, unsigned& r2,
                                        unsigned& r3, unsigned addr) {
    asm volatile("ldmatrix.sync.aligned.m8n8.x4.shared.b16 {%0,%1,%2,%3}, [%4];"
                 : "=r"(r0), "=r"(r1), "=r"(r2), "=r"(r3) : "r"(addr));
}

// == pre-pass: transpose BOTH embeddings [b][d][x] fp32 -> [b][x][d] fp16 ===
// blockIdx.z in [0, 2*BATCH): low 4 bits = batch, bit 4 selects tensor.
__global__ __launch_bounds__(256)
void conv_transpose2(const float* __restrict__ inA, const float* __restrict__ inB) {
    __shared__ float t[32][33];
    const int z  = blockIdx.z;
    const int b  = z & (BATCH - 1);
    const int sel = z >> 4;
    const float* in = sel ? inB : inA;
    __half* out = sel ? g_b16 : g_a16;

    const int d0 = blockIdx.y * 32;
    const int x0 = blockIdx.x * 32;
    const int tx = threadIdx.x & 31;
    const int ty = threadIdx.x >> 5;

    const float* src = in + (size_t)b * DK * NN + (size_t)d0 * NN + x0;
    #pragma unroll
    for (int i = 0; i < 4; ++i)
        t[ty + i * 8][tx] = src[(size_t)(ty + i * 8) * NN + tx];
    __syncthreads();

    __half* dst = out + (size_t)b * NN * DK + (size_t)x0 * DK + d0;
    #pragma unroll
    for (int i = 0; i < 4; ++i)
        dst[(size_t)(ty + i * 8) * DK + tx] = __float2half_rn(t[tx][ty + i * 8]);
}

// ============== pre-pass: pack V rows (high + residual) ====================
__global__ __launch_bounds__(256)
void prep_v(const float* __restrict__ tgt, const float* __restrict__ tdm,
            const float* __restrict__ tim) {
    const int b = blockIdx.y;
    const int m = blockIdx.x * 256 + threadIdx.x;
    const float* t0 = tgt + (size_t)b * 3 * MM;
    __half* dst = g_v16 + (size_t)b * 16 * MM;
    float v[5];
    v[0] = t0[m];
    v[1] = t0[MM + m];
    v[2] = t0[2 * MM + m];
    v[3] = tdm[(size_t)b * MM + m];
    v[4] = tim[(size_t)b * MM + m];
    #pragma unroll
    for (int j = 0; j < 5; ++j) {
        __half h = __float2half_rn(v[j]);
        dst[j * MM + m] = h;
        dst[(8 + j) * MM + m] = __float2half_rn(v[j] - __half2float(h));
    }
    const __half z = __float2half_rn(0.f);
    dst[5 * MM + m] = __float2half_rn(1.f);
    dst[6 * MM + m] = z;  dst[7 * MM + m] = z;
    dst[13 * MM + m] = z; dst[14 * MM + m] = z; dst[15 * MM + m] = z;
}

// ========= fused: scores GEMM(fp16, ldmatrix) + exp2 + compensated PV-MMA ==
// 8 warps: warp grid 4(m) x 2(n), warp tile 32 rows x 64 cols.
__global__ __launch_bounds__(THREADS, 2)
void fused_attn() {
    extern __shared__ char smraw[];
    __half* As = (__half*)smraw;                       // [2*BMT][LDK]
    __half* Bs = As + SM_AH;                           // [2*BNT][LDK]
    __half* Vh = Bs + SM_BH;                           // 2 buffers [16][VLD]
    float*  Pv = (float*)(Vh + 2 * SM_VH);             // [2][128][9]

    const int nt = blockIdx.x;
    const int mh = blockIdx.y;
    const int b  = blockIdx.z;
    const int n0 = nt * BMT;
    const int mbase = mh * NMT_LOC * BNT;

    const __half* Ab = g_a16 + (size_t)b * NN * DK;
    const __half* Bb = g_b16 + (size_t)b * MM * DK;
    const __half* Vb = g_v16 + (size_t)b * 16 * MM;

    const int tid  = threadIdx.x;
    const int lane = tid & 31;
    const int warp = tid >> 5;       // 0..7
    const int wm = warp & 3;         // 0..3 -> 32 rows each
    const int wn = warp >> 2;        // 0..1 -> 64 cols each
    const int g  = lane >> 2;        // 0..7
    const int tq = lane & 3;         // 0..3

    // ldmatrix per-lane offsets (in halves).
    const int q = lane >> 3;
    const int a_off = ((lane & 7) + ((q & 1) << 3)) * LDK + ((q >> 1) << 3);
    const int b_off = ((lane & 7) + ((q >> 1) << 3)) * LDK + ((q & 1) << 3);
    const unsigned As_u = smem_u32(As);
    const unsigned Bs_u = smem_u32(Bs);

    float pvH[2][4], pvR[2][4];
    #pragma unroll
    for (int i = 0; i < 2; ++i)
        #pragma unroll
        for (int c = 0; c < 4; ++c) { pvH[i][c] = 0.f; pvR[i][c] = 0.f; }

    auto issue_stage = [&](int m0, int kt, int s) {
        const int k0 = kt * BK;
        #pragma unroll
        for (int i = 0; i < 4; ++i) {
            const int idx = tid + i * THREADS;    // 0..1023
            const int r = idx >> 3;               // row 0..127
            const int cs = (idx & 7) * 8;         // half offset 0..56
            cp_async16(&As[(s * BMT + r) * LDK + cs], &Ab[(size_t)(n0 + r) * DK + k0 + cs]);
            cp_async16(&Bs[(s * BNT + r) * LDK + cs], &Bb[(size_t)(m0 + r) * DK + k0 + cs]);
        }
    };
    auto issue_V = [&](int m0, int vbuf) {
        __half* Vd = Vh + vbuf * SM_VH;
        const int j = tid >> 4;               // row 0..15
        const int c = (tid & 15) * 8;         // 0..120
        cp_async16(&Vd[j * VLD + c], &Vb[(size_t)j * MM + m0 + c]);
    };

    issue_stage(mbase, 0, 0);
    issue_V(mbase, 0);
    cp_commit();

    // exp(x/sqrt(512)) = exp2(x * log2(e)/sqrt(512))
    const float scale2 = 0.063763115930097f;

    for (int mt = 0; mt < NMT_LOC; ++mt) {
        const int m0 = mbase + mt * BNT;

        float acc[2][8][4];
        #pragma unroll
        for (int i = 0; i < 2; ++i)
            #pragma unroll
            for (int j = 0; j < 8; ++j)
                #pragma unroll
                for (int c = 0; c < 4; ++c) acc[i][j][c] = 0.f;

        // -------- S = A·B^T  (128x128 tile over K=512, BK=64 stages) --------
        for (int kt = 0; kt < NKT; ++kt) {
            cp_wait0();
            __syncthreads();   // stage kt arrived AND all warps done with kt-1
            if (kt + 1 < NKT) { issue_stage(m0, kt + 1, (kt + 1) & 1); cp_commit(); }

            const int s = kt & 1;
            #pragma unroll
            for (int ks = 0; ks < 4; ++ks) {
                const int kbase = ks * 16;
                unsigned afr[2][4], bfr[8][2];
                #pragma unroll
                for (int mi = 0; mi < 2; ++mi) {
                    const unsigned aaddr = As_u + 2u *
                        (unsigned)((s * BMT + wm * 32 + mi * 16) * LDK + kbase + a_off);
                    ldsm_x4(afr[mi][0], afr[mi][1], afr[mi][2], afr[mi][3], aaddr);
                }
                #pragma unroll
                for (int nip = 0; nip < 4; ++nip) {
                    const unsigned baddr = Bs_u + 2u *
                        (unsigned)((s * BNT + wn * 64 + nip * 16) * LDK + kbase + b_off);
                    ldsm_x4(bfr[2 * nip][0], bfr[2 * nip][1],
                            bfr[2 * nip + 1][0], bfr[2 * nip + 1][1], baddr);
                }
                #pragma unroll
                for (int mi = 0; mi < 2; ++mi)
                    #pragma unroll
                    for (int ni = 0; ni < 8; ++ni) {
                        asm volatile(
                            "mma.sync.aligned.m16n8k16.row.col.f32.f16.f16.f32 "
                            "{%0,%1,%2,%3}, {%4,%5,%6,%7}, {%8,%9}, {%0,%1,%2,%3};"
                            : "+f"(acc[mi][ni][0]), "+f"(acc[mi][ni][1]),
                              "+f"(acc[mi][ni][2]), "+f"(acc[mi][ni][3])
                            : "r"(afr[mi][0]), "r"(afr[mi][1]),
                              "r"(afr[mi][2]), "r"(afr[mi][3]),
                              "r"(bfr[ni][0]), "r"(bfr[ni][1]));
                    }
            }
            // no end barrier: next stage's top barrier provides the WAR guard
        }

        // overlap next tile's first stage + V with the exp/PV phase
        if (mt + 1 < NMT_LOC) {
            issue_stage(m0 + BNT, 0, 0);
            issue_V(m0 + BNT, (mt + 1) & 1);
            cp_commit();
        }

        // -------- E = exp2(scale2*S) in registers --------
        #pragma unroll
        for (int mi = 0; mi < 2; ++mi)
            #pragma unroll
            for (int ni = 0; ni < 8; ++ni)
                #pragma unroll
                for (int c = 0; c < 4; ++c)
                    acc[mi][ni][c] = exp2f(acc[mi][ni][c] * scale2);

        // -------- compensated PV += E · V^T (this warp's 64 score cols) ----
        const __half* Vc = Vh + (mt & 1) * SM_VH;
        #pragma unroll
        for (int kk = 0; kk < 4; ++kk) {
            const int koff = wn * 64 + kk * 16;
            unsigned vh0 = *(const unsigned*)(Vc + g * VLD + koff + 2 * tq);
            unsigned vh1 = *(const unsigned*)(Vc + g * VLD + koff + 2 * tq + 8);
            unsigned vr0 = *(const unsigned*)(Vc + (8 + g) * VLD + koff + 2 * tq);
            unsigned vr1 = *(const unsigned*)(Vc + (8 + g) * VLD + koff + 2 * tq + 8);
            #pragma unroll
            for (int mi = 0; mi < 2; ++mi) {
                __half2 eh[4], er[4];
                #pragma unroll
                for (int p = 0; p < 2; ++p) {
                    const float e0 = acc[mi][2 * kk + p][0];
                    const float e1 = acc[mi][2 * kk + p][1];
                    const float e2 = acc[mi][2 * kk + p][2];
                    const float e3 = acc[mi][2 * kk + p][3];
                    __half2 h01 = __floats2half2_rn(e0, e1);
                    __half2 h23 = __floats2half2_rn(e2, e3);
                    float2 f01 = __half22float2(h01);
                    float2 f23 = __half22float2(h23);
                    eh[2 * p]     = h01;
                    eh[2 * p + 1] = h23;
                    er[2 * p]     = __floats2half2_rn(e0 - f01.x, e1 - f01.y);
                    er[2 * p + 1] = __floats2half2_rn(e2 - f23.x, e3 - f23.y);
                }
                asm volatile(
                    "mma.sync.aligned.m16n8k16.row.col.f32.f16.f16.f32 "
                    "{%0,%1,%2,%3}, {%4,%5,%6,%7}, {%8,%9}, {%0,%1,%2,%3};"
                    : "+f"(pvH[mi][0]), "+f"(pvH[mi][1]),
                      "+f"(pvH[mi][2]), "+f"(pvH[mi][3])
                    : "r"(*(unsigned*)&eh[0]), "r"(*(unsigned*)&eh[1]),
                      "r"(*(unsigned*)&eh[2]), "r"(*(unsigned*)&eh[3]),
                      "r"(vh0), "r"(vh1));
                asm volatile(
                    "mma.sync.aligned.m16n8k16.row.col.f32.f16.f16.f32 "
                    "{%0,%1,%2,%3}, {%4,%5,%6,%7}, {%8,%9}, {%0,%1,%2,%3};"
                    : "+f"(pvH[mi][0]), "+f"(pvH[mi][1]),
                      "+f"(pvH[mi][2]), "+f"(pvH[mi][3])
                    : "r"(*(unsigned*)&er[0]), "r"(*(unsigned*)&er[1]),
                      "r"(*(unsigned*)&er[2]), "r"(*(unsigned*)&er[3]),
                      "r"(vh0), "r"(vh1));
                asm volatile(
                    "mma.sync.aligned.m16n8k16.row.col.f32.f16.f16.f32 "
                    "{%0,%1,%2,%3}, {%4,%5,%6,%7}, {%8,%9}, {%0,%1,%2,%3};"
                    : "+f"(pvR[mi][0]), "+f"(pvR[mi][1]),
                      "+f"(pvR[mi][2]), "+f"(pvR[mi][3])
                    : "r"(*(unsigned*)&eh[0]), "r"(*(unsigned*)&eh[1]),
                      "r"(*(unsigned*)&eh[2]), "r"(*(unsigned*)&eh[3]),
                      "r"(vr0), "r"(vr1));
            }
        }
    }

    // -------- cross-warp PV merge (wn=0 stores, wn=1 adds) --------
    float* PvH = Pv;
    float* PvR = Pv + BMT * 9;
    __syncthreads();
    if (wn == 0) {
        #pragma unroll
        for (int mi = 0; mi < 2; ++mi) {
            const int r = wm * 32 + mi * 16 + g;
            PvH[r * 9 + 2 * tq]           = pvH[mi][0];
            PvH[r * 9 + 2 * tq + 1]       = pvH[mi][1];
            PvH[(r + 8) * 9 + 2 * tq]     = pvH[mi][2];
            PvH[(r + 8) * 9 + 2 * tq + 1] = pvH[mi][3];
            PvR[r * 9 + 2 * tq]           = pvR[mi][0];
            PvR[r * 9 + 2 * tq + 1]       = pvR[mi][1];
            PvR[(r + 8) * 9 + 2 * tq]     = pvR[mi][2];
            PvR[(r + 8) * 9 + 2 * tq + 1] = pvR[mi][3];
        }
    }
    __syncthreads();
    if (wn == 1) {
        #pragma unroll
        for (int mi = 0; mi < 2; ++mi) {
            const int r = wm * 32 + mi * 16 + g;
            PvH[r * 9 + 2 * tq]           += pvH[mi][0];
            PvH[r * 9 + 2 * tq + 1]       += pvH[mi][1];
            PvH[(r + 8) * 9 + 2 * tq]     += pvH[mi][2];
            PvH[(r + 8) * 9 + 2 * tq + 1] += pvH[mi][3];
            PvR[r * 9 + 2 * tq]           += pvR[mi][0];
            PvR[r * 9 + 2 * tq + 1]       += pvR[mi][1];
            PvR[(r + 8) * 9 + 2 * tq]     += pvR[mi][2];
            PvR[(r + 8) * 9 + 2 * tq + 1] += pvR[mi][3];
        }
    }
    __syncthreads();

    // -------- write unnormalized partial (rows 0-4 = pv, row 5 = l) --------
    if (tid < BMT) {
        float* out = g_pv + (((size_t)b * MSPLIT + mh) * 6) * NN + n0 + tid;
        #pragma unroll
        for (int j = 0; j < 6; ++j)
            out[j * NN] = PvH[tid * 9 + j] + PvR[tid * 9 + j];
    }
}

// ======================= reductions =========================================
__device__ __forceinline__ float warp_sum(float v) {
    #pragma unroll
    for (int o = 16; o; o >>= 1) v += __shfl_down_sync(0xffffffffu, v, o);
    return v;
}
__device__ __forceinline__ float warp_max(float v) {
    #pragma unroll
    for (int o = 16; o; o >>= 1) v = fmaxf(v, __shfl_down_sync(0xffffffffu, v, o));
    return v;
}
__device__ __forceinline__ float warp_min(float v) {
    #pragma unroll
    for (int o = 16; o; o >>= 1) v = fminf(v, __shfl_down_sync(0xffffffffu, v, o));
    return v;
}

// ======================= finalize: merge partials, mask, H, SVD, R,t =======
// 512 threads (16 warps) to halve the per-pass loop trip counts.
__device__ __forceinline__ float sigm(float x) { return 1.f / (1.f + __expf(-x)); }

__global__ __launch_bounds__(512)
void finalize_kernel(const float* __restrict__ src,
                     const float* __restrict__ sdm,
                     const float* __restrict__ sim,
                     float* __restrict__ out) {
    __shared__ float scorr[5 * NN];
    __shared__ float part[16][9];
    __shared__ float bc[20];

    const int b = blockIdx.x;
    const int tid  = threadIdx.x;
    const int lane = tid & 31;
    const int w    = tid >> 5;

    const float* S  = src + (size_t)b * 3 * NN;
    const float* Dm = sdm + (size_t)b * NN;
    const float* Im = sim + (size_t)b * NN;
    const float* P  = g_pv + ((size_t)b * MSPLIT * 6) * NN;

    // ---- merge the M-partials (fixed order -> deterministic) ----
    for (int n = tid; n < NN; n += 512) {
        float s[6];
        #pragma unroll
        for (int j = 0; j < 6; ++j) {
            float acc = 0.f;
            #pragma unroll
            for (int mh = 0; mh < MSPLIT; ++mh)
                acc += P[((size_t)mh * 6 + j) * NN + n];
            s[j] = acc;
        }
        const float inv = 1.f / s[5];
        #pragma unroll
        for (int j = 0; j < 5; ++j) scorr[j * NN + n] = s[j] * inv;
    }
    __syncthreads();

    // ---- pass 1: means + mask min/max ----
    float a[8] = {0, 0, 0, 0, 0, 0, INFINITY, -INFINITY};
    for (int n = tid; n < NN; n += 512) {
        a[0] += S[n]; a[1] += S[NN + n]; a[2] += S[2 * NN + n];
        a[3] += scorr[n]; a[4] += scorr[NN + n]; a[5] += scorr[2 * NN + n];
        float dep = 0.5f * (Dm[n] + scorr[3 * NN + n]);
        float img = 0.5f * (Im[n] + scorr[4 * NN + n]);
        float mk = sigm(dep) * sigm(img);
        a[6] = fminf(a[6], mk);
        a[7] = fmaxf(a[7], mk);
    }
    #pragma unroll
    for (int j = 0; j < 6; ++j) a[j] = warp_sum(a[j]);
    a[6] = warp_min(a[6]);
    a[7] = warp_max(a[7]);
    if (lane == 0)
        #pragma unroll
        for (int j = 0; j < 8; ++j) part[w][j] = a[j];
    __syncthreads();
    if (tid < 8) {
        float r = part[0][tid];
        if (tid < 6)      { for (int i = 1; i < 16; ++i) r += part[i][tid];        r *= (1.f / NN); }
        else if (tid == 6){ for (int i = 1; i < 16; ++i) r = fminf(r, part[i][6]); }
        else              { for (int i = 1; i < 16; ++i) r = fmaxf(r, part[i][7]); }
        bc[tid] = r;
    }
    __syncthreads();
    const float sm0 = bc[0], sm1 = bc[1], sm2 = bc[2];
    const float cm0 = bc[3], cm1 = bc[4], cm2 = bc[5];
    const float MN = bc[6], MX = bc[7];
    const float invden = 1.f / fmaxf(MX - MN, 1e-6f);

    // ---- pass 2: weighted covariance H ----
    float h[9];
    #pragma unroll
    for (int i = 0; i < 9; ++i) h[i] = 0.f;
    for (int n = tid; n < NN; n += 512) {
        float dep = 0.5f * (Dm[n] + scorr[3 * NN + n]);
        float img = 0.5f * (Im[n] + scorr[4 * NN + n]);
        float wt = (sigm(dep) * sigm(img) - MN) * invden;
        float x0 = S[n] - sm0, x1 = S[NN + n] - sm1, x2 = S[2 * NN + n] - sm2;
        float y0 = scorr[n] - cm0, y1 = scorr[NN + n] - cm1, y2 = scorr[2 * NN + n] - cm2;
        h[0] += wt * x0 * y0; h[1] += wt * x0 * y1; h[2] += wt * x0 * y2;
        h[3] += wt * x1 * y0; h[4] += wt * x1 * y1; h[5] += wt * x1 * y2;
        h[6] += wt * x2 * y0; h[7] += wt * x2 * y1; h[8] += wt * x2 * y2;
    }
    #pragma unroll
    for (int i = 0; i < 9; ++i) h[i] = warp_sum(h[i]);
    __syncthreads();
    if (lane == 0)
        #pragma unroll
        for (int i = 0; i < 9; ++i) part[w][i] = h[i];
    __syncthreads();
    if (tid < 9) {
        float r = part[0][tid];
        for (int i = 1; i < 16; ++i) r += part[i][tid];
        bc[8 + tid] = r;
    }
    __syncthreads();

    if (tid == 0) {
        double Hd[3][3];
        for (int i = 0; i < 3; ++i)
            for (int j = 0; j < 3; ++j) Hd[i][j] = (double)bc[8 + i * 3 + j];

        double A[3][3];
        for (int i = 0; i < 3; ++i)
            for (int j = 0; j < 3; ++j) {
                double s = 0;
                for (int k = 0; k < 3; ++k) s += Hd[k][i] * Hd[k][j];
                A[i][j] = s;
            }
        double V[3][3] = {{1, 0, 0}, {0, 1, 0}, {0, 0, 1}};
        const int pr[3] = {0, 0, 1}, qr[3] = {1, 2, 2};
        for (int sweep = 0; sweep < 8; ++sweep) {
            for (int pi = 0; pi < 3; ++pi) {
                const int p = pr[pi], q = qr[pi];
                double apq = A[p][q];
                if (fabs(apq) < 1e-300) continue;
                double theta = (A[q][q] - A[p][p]) / (2.0 * apq);
                double t = ((theta >= 0.0) ? 1.0 : -1.0) /
                           (fabs(theta) + sqrt(1.0 + theta * theta));
                double cth = 1.0 / sqrt(1.0 + t * t);
                double sth = t * cth;
                for (int k = 0; k < 3; ++k) {
                    double akp = A[k][p], akq = A[k][q];
                    A[k][p] = cth * akp - sth * akq;
                    A[k][q] = sth * akp + cth * akq;
                }
                for (int k = 0; k < 3; ++k) {
                    double apk = A[p][k], aqk = A[q][k];
                    A[p][k] = cth * apk - sth * aqk;
                    A[q][k] = sth * apk + cth * aqk;
                }
                for (int k = 0; k < 3; ++k) {
                    double vkp = V[k][p], vkq = V[k][q];
                    V[k][p] = cth * vkp - sth * vkq;
                    V[k][q] = sth * vkp + cth * vkq;
                }
            }
        }
        double w3[3] = {A[0][0], A[1][1], A[2][2]};
        for (int i = 0; i < 2; ++i)
            for (int j = i + 1; j < 3; ++j)
                if (w3[j] > w3[i]) {
                    double tw = w3[i]; w3[i] = w3[j]; w3[j] = tw;
                    for (int k = 0; k < 3; ++k) {
                        double tv = V[k][i]; V[k][i] = V[k][j]; V[k][j] = tv;
                    }
                }
        double U[3][3];
        for (int j = 0; j < 3; ++j) {
            double sig = sqrt(w3[j] > 0.0 ? w3[j] : 0.0);
            double inv = 1.0 / (sig > 1e-30 ? sig : 1e-30);
            for (int i = 0; i < 3; ++i)
                U[i][j] = (Hd[i][0] * V[0][j] + Hd[i][1] * V[1][j] + Hd[i][2] * V[2][j]) * inv;
        }
        double R[3][3];
        for (int i = 0; i < 3; ++i)
            for (int j = 0; j < 3; ++j)
                R[i][j] = V[i][0] * U[j][0] + V[i][1] * U[j][1] + V[i][2] * U[j][2];
        double det = R[0][0] * (R[1][1] * R[2][2] - R[1][2] * R[2][1])
                   - R[0][1] * (R[1][0] * R[2][2] - R[1][2] * R[2][0])
                   + R[0][2] * (R[1][0] * R[2][1] - R[1][1] * R[2][0]);
        if (det < 0.0) {
            for (int k = 0; k < 3; ++k) V[k][2] = -V[k][2];
            for (int i = 0; i < 3; ++i)
                for (int j = 0; j < 3; ++j)
                    R[i][j] = V[i][0] * U[j][0] + V[i][1] * U[j][1] + V[i][2] * U[j][2];
        }
        const double smv[3] = {sm0, sm1, sm2};
        const double cmv[3] = {cm0, cm1, cm2};

        float* Rout = out + b * 9;
        float* tout = out + BATCH * 9 + b * 3;
        for (int i = 0; i < 3; ++i) {
            for (int j = 0; j < 3; ++j) Rout[i * 3 + j] = (float)R[i][j];
            double ti = -(R[i][0] * smv[0] + R[i][1] * smv[1] + R[i][2] * smv[2]) + cmv[i];
            tout[i] = (float)ti;
        }
    }
}

// ======================= launch ============================================
extern "C" void kernel_launch(void* const* d_in, const int* in_sizes, int n_in,
                              void* d_out, int out_size) {
    const float* src_emb = (const float*)d_in[0];
    const float* tgt_emb = (const float*)d_in[1];
    const float* src     = (const float*)d_in[2];
    const float* tgt     = (const float*)d_in[3];
    const float* sdm     = (const float*)d_in[4];
    const float* tdm     = (const float*)d_in[5];
    const float* sim     = (const float*)d_in[6];
    const float* tim     = (const float*)d_in[7];
    float* out = (float*)d_out;

    cudaFuncSetAttribute(fused_attn, cudaFuncAttributeMaxDynamicSharedMemorySize,
                         SM_TOTAL_BYTES);

    dim3 gc(NN / 32, DK / 32, 2 * BATCH);
    conv_transpose2<<<gc, 256>>>(src_emb, tgt_emb);
    dim3 gv(MM / 256, BATCH);
    prep_v<<<gv, 256>>>(tgt, tdm, tim);

    dim3 grid(NN / BMT, MSPLIT, BATCH);   // 16 x 4 x 16 = 1024 blocks
    fused_attn<<<grid, THREADS, SM_TOTAL_BYTES>>>();
    finalize_kernel<<<BATCH, 512>>>(src, sdm, sim, out);
}

// round 17
// speedup vs baseline: 1.0540x; 1.0160x over previous
#include <cuda_runtime.h>
#include <cuda_fp16.h>
#include <math.h>

#define BATCH 16
#define DK    512
#define NN    2048
#define MM    2048

#define BMT 128             // N rows per block
#define BNT 128             // M cols per tile
#define BK  64              // K per stage (4 x m16n8k16)
#define LDK 72              // halves per row (64 + 8 pad)
#define NKT (DK / BK)       // 8
#define MSPLIT 4            // m-tile groups (blocks) per n-tile
#define NMT_LOC (MM / BNT / MSPLIT)   // 4 m-tiles per block
#define VLD 136             // Vh row stride in halves
#define THREADS 256

// halves
#define SM_AH   (2 * BMT * LDK)        // 18432
#define SM_BH   (2 * BNT * LDK)        // 18432
#define SM_VH   (16 * VLD)             // 2176 per buffer
// floats
#define SM_PV   (2 * BMT * 9)
#define SM_TOTAL_BYTES ((SM_AH + SM_BH + 2 * SM_VH) * 2 + SM_PV * 4)  // 91648

__device__ __half g_a16[(size_t)BATCH * NN * DK];   // [b][n][d]
__device__ __half g_b16[(size_t)BATCH * MM * DK];   // [b][m][d]
__device__ __half g_v16[(size_t)BATCH * 16 * MM];   // [b][16][m]
__device__ float  g_pv[(size_t)BATCH * MSPLIT * 6 * NN];  // unnormalized partials

__device__ __forceinline__ unsigned smem_u32(const void* p) {
    unsigned a;
    asm("{ .reg .u64 t; cvta.to.shared.u64 t, %1; cvt.u32.u64 %0, t; }" : "=r"(a) : "l"(p));
    return a;
}
__device__ __forceinline__ void cp_async16(void* smem, const void* gmem) {
    unsigned s = (unsigned)__cvta_generic_to_shared(smem);
    asm volatile("cp.async.cg.shared.global [%0], [%1], 16;\n" :: "r"(s), "l"(gmem));
}
__device__ __forceinline__ void cp_commit() { asm volatile("cp.async.commit_group;\n"); }
__device__ __forceinline__ void cp_wait0()  { asm volatile("cp.async.wait_group 0;\n"); }

__device__ __forceinline__ void ldsm_x4(unsigned& r0, unsigned& r1, unsigned& r2,
                                        unsigned& r3, unsigned addr) {
    asm volatile("ldmatrix.sync.aligned.m8n8.x4.shared.b16 {%0,%1,%2,%3}, [%4];"
                 : "=r"(r0), "=r"(r1), "=r"(r2), "=r"(r3) : "r"(addr));
}

// == pre-pass: transpose BOTH embeddings [b][d][x] fp32 -> [b][x][d] fp16 ===
__global__ __launch_bounds__(256)
void conv_transpose2(const float* __restrict__ inA, const float* __restrict__ inB) {
    __shared__ float t[32][33];
    const int z  = blockIdx.z;
    const int b  = z & (BATCH - 1);
    const int sel = z >> 4;
    const float* in = sel ? inB : inA;
    __half* out = sel ? g_b16 : g_a16;

    const int d0 = blockIdx.y * 32;
    const int x0 = blockIdx.x * 32;
    const int tx = threadIdx.x & 31;
    const int ty = threadIdx.x >> 5;

    const float* src = in + (size_t)b * DK * NN + (size_t)d0 * NN + x0;
    #pragma unroll
    for (int i = 0; i < 4; ++i)
        t[ty + i * 8][tx] = src[(size_t)(ty + i * 8) * NN + tx];
    __syncthreads();

    __half* dst = out + (size_t)b * NN * DK + (size_t)x0 * DK + d0;
    #pragma unroll
    for (int i = 0; i < 4; ++i)
        dst[(size_t)(ty + i * 8) * DK + tx] = __float2half_rn(t[tx][ty + i * 8]);
}

// ============== pre-pass: pack V rows (high + residual) ====================
__global__ __launch_bounds__(256)
void prep_v(const float* __restrict__ tgt, const float* __restrict__ tdm,
            const float* __restrict__ tim) {
    const int b = blockIdx.y;
    const int m = blockIdx.x * 256 + threadIdx.x;
    const float* t0 = tgt + (size_t)b * 3 * MM;
    __half* dst = g_v16 + (size_t)b * 16 * MM;
    float v[5];
    v[0] = t0[m];
    v[1] = t0[MM + m];
    v[2] = t0[2 * MM + m];
    v[3] = tdm[(size_t)b * MM + m];
    v[4] = tim[(size_t)b * MM + m];
    #pragma unroll
    for (int j = 0; j < 5; ++j) {
        __half h = __float2half_rn(v[j]);
        dst[j * MM + m] = h;
        dst[(8 + j) * MM + m] = __float2half_rn(v[j] - __half2float(h));
    }
    const __half z = __float2half_rn(0.f);
    dst[5 * MM + m] = __float2half_rn(1.f);
    dst[6 * MM + m] = z;  dst[7 * MM + m] = z;
    dst[13 * MM + m] = z; dst[14 * MM + m] = z; dst[15 * MM + m] = z;
}

// ========= fused: scores GEMM(fp16, ldmatrix) + exp2 + compensated PV-MMA ==
// 8 warps: warp grid 4(m) x 2(n), warp tile 32 rows x 64 cols.
__global__ __launch_bounds__(THREADS, 2)
void fused_attn() {
    extern __shared__ char smraw[];
    __half* As = (__half*)smraw;                       // [2*BMT][LDK]
    __half* Bs = As + SM_AH;                           // [2*BNT][LDK]
    __half* Vh = Bs + SM_BH;                           // 2 buffers [16][VLD]
    float*  Pv = (float*)(Vh + 2 * SM_VH);             // [2][128][9]

    const int nt = blockIdx.x;
    const int mh = blockIdx.y;
    const int b  = blockIdx.z;
    const int n0 = nt * BMT;
    const int mbase = mh * NMT_LOC * BNT;

    const __half* Ab = g_a16 + (size_t)b * NN * DK;
    const __half* Bb = g_b16 + (size_t)b * MM * DK;
    const __half* Vb = g_v16 + (size_t)b * 16 * MM;

    const int tid  = threadIdx.x;
    const int lane = tid & 31;
    const int warp = tid >> 5;       // 0..7
    const int wm = warp & 3;         // 0..3 -> 32 rows each
    const int wn = warp >> 2;        // 0..1 -> 64 cols each
    const int g  = lane >> 2;        // 0..7
    const int tq = lane & 3;         // 0..3

    const int q = lane >> 3;
    const int a_off = ((lane & 7) + ((q & 1) << 3)) * LDK + ((q >> 1) << 3);
    const int b_off = ((lane & 7) + ((q >> 1) << 3)) * LDK + ((q & 1) << 3);
    const unsigned As_u = smem_u32(As);
    const unsigned Bs_u = smem_u32(Bs);

    float pvH[2][4], pvR[2][4];
    #pragma unroll
    for (int i = 0; i < 2; ++i)
        #pragma unroll
        for (int c = 0; c < 4; ++c) { pvH[i][c] = 0.f; pvR[i][c] = 0.f; }

    auto issue_stage = [&](int m0, int kt, int s) {
        const int k0 = kt * BK;
        #pragma unroll
        for (int i = 0; i < 4; ++i) {
            const int idx = tid + i * THREADS;    // 0..1023
            const int r = idx >> 3;               // row 0..127
            const int cs = (idx & 7) * 8;         // half offset 0..56
            cp_async16(&As[(s * BMT + r) * LDK + cs], &Ab[(size_t)(n0 + r) * DK + k0 + cs]);
            cp_async16(&Bs[(s * BNT + r) * LDK + cs], &Bb[(size_t)(m0 + r) * DK + k0 + cs]);
        }
    };
    auto issue_V = [&](int m0, int vbuf) {
        __half* Vd = Vh + vbuf * SM_VH;
        const int j = tid >> 4;               // row 0..15
        const int c = (tid & 15) * 8;         // 0..120
        cp_async16(&Vd[j * VLD + c], &Vb[(size_t)j * MM + m0 + c]);
    };

    issue_stage(mbase, 0, 0);
    issue_V(mbase, 0);
    cp_commit();

    const float scale2 = 0.063763115930097f;   // log2(e)/sqrt(512)

    for (int mt = 0; mt < NMT_LOC; ++mt) {
        const int m0 = mbase + mt * BNT;

        float acc[2][8][4];
        #pragma unroll
        for (int i = 0; i < 2; ++i)
            #pragma unroll
            for (int j = 0; j < 8; ++j)
                #pragma unroll
                for (int c = 0; c < 4; ++c) acc[i][j][c] = 0.f;

        for (int kt = 0; kt < NKT; ++kt) {
            cp_wait0();
            __syncthreads();
            if (kt + 1 < NKT) { issue_stage(m0, kt + 1, (kt + 1) & 1); cp_commit(); }

            const int s = kt & 1;
            #pragma unroll
            for (int ks = 0; ks < 4; ++ks) {
                const int kbase = ks * 16;
                unsigned afr[2][4], bfr[8][2];
                #pragma unroll
                for (int mi = 0; mi < 2; ++mi) {
                    const unsigned aaddr = As_u + 2u *
                        (unsigned)((s * BMT + wm * 32 + mi * 16) * LDK + kbase + a_off);
                    ldsm_x4(afr[mi][0], afr[mi][1], afr[mi][2], afr[mi][3], aaddr);
                }
                #pragma unroll
                for (int nip = 0; nip < 4; ++nip) {
                    const unsigned baddr = Bs_u + 2u *
                        (unsigned)((s * BNT + wn * 64 + nip * 16) * LDK + kbase + b_off);
                    ldsm_x4(bfr[2 * nip][0], bfr[2 * nip][1],
                            bfr[2 * nip + 1][0], bfr[2 * nip + 1][1], baddr);
                }
                #pragma unroll
                for (int mi = 0; mi < 2; ++mi)
                    #pragma unroll
                    for (int ni = 0; ni < 8; ++ni) {
                        asm volatile(
                            "mma.sync.aligned.m16n8k16.row.col.f32.f16.f16.f32 "
                            "{%0,%1,%2,%3}, {%4,%5,%6,%7}, {%8,%9}, {%0,%1,%2,%3};"
                            : "+f"(acc[mi][ni][0]), "+f"(acc[mi][ni][1]),
                              "+f"(acc[mi][ni][2]), "+f"(acc[mi][ni][3])
                            : "r"(afr[mi][0]), "r"(afr[mi][1]),
                              "r"(afr[mi][2]), "r"(afr[mi][3]),
                              "r"(bfr[ni][0]), "r"(bfr[ni][1]));
                    }
            }
        }

        if (mt + 1 < NMT_LOC) {
            issue_stage(m0 + BNT, 0, 0);
            issue_V(m0 + BNT, (mt + 1) & 1);
            cp_commit();
        }

        #pragma unroll
        for (int mi = 0; mi < 2; ++mi)
            #pragma unroll
            for (int ni = 0; ni < 8; ++ni)
                #pragma unroll
                for (int c = 0; c < 4; ++c)
                    acc[mi][ni][c] = exp2f(acc[mi][ni][c] * scale2);

        const __half* Vc = Vh + (mt & 1) * SM_VH;
        #pragma unroll
        for (int kk = 0; kk < 4; ++kk) {
            const int koff = wn * 64 + kk * 16;
            unsigned vh0 = *(const unsigned*)(Vc + g * VLD + koff + 2 * tq);
            unsigned vh1 = *(const unsigned*)(Vc + g * VLD + koff + 2 * tq + 8);
            unsigned vr0 = *(const unsigned*)(Vc + (8 + g) * VLD + koff + 2 * tq);
            unsigned vr1 = *(const unsigned*)(Vc + (8 + g) * VLD + koff + 2 * tq + 8);
            #pragma unroll
            for (int mi = 0; mi < 2; ++mi) {
                __half2 eh[4], er[4];
                #pragma unroll
                for (int p = 0; p < 2; ++p) {
                    const float e0 = acc[mi][2 * kk + p][0];
                    const float e1 = acc[mi][2 * kk + p][1];
                    const float e2 = acc[mi][2 * kk + p][2];
                    const float e3 = acc[mi][2 * kk + p][3];
                    __half2 h01 = __floats2half2_rn(e0, e1);
                    __half2 h23 = __floats2half2_rn(e2, e3);
                    float2 f01 = __half22float2(h01);
                    float2 f23 = __half22float2(h23);
                    eh[2 * p]     = h01;
                    eh[2 * p + 1] = h23;
                    er[2 * p]     = __floats2half2_rn(e0 - f01.x, e1 - f01.y);
                    er[2 * p + 1] = __floats2half2_rn(e2 - f23.x, e3 - f23.y);
                }
                asm volatile(
                    "mma.sync.aligned.m16n8k16.row.col.f32.f16.f16.f32 "
                    "{%0,%1,%2,%3}, {%4,%5,%6,%7}, {%8,%9}, {%0,%1,%2,%3};"
                    : "+f"(pvH[mi][0]), "+f"(pvH[mi][1]),
                      "+f"(pvH[mi][2]), "+f"(pvH[mi][3])
                    : "r"(*(unsigned*)&eh[0]), "r"(*(unsigned*)&eh[1]),
                      "r"(*(unsigned*)&eh[2]), "r"(*(unsigned*)&eh[3]),
                      "r"(vh0), "r"(vh1));
                asm volatile(
                    "mma.sync.aligned.m16n8k16.row.col.f32.f16.f16.f32 "
                    "{%0,%1,%2,%3}, {%4,%5,%6,%7}, {%8,%9}, {%0,%1,%2,%3};"
                    : "+f"(pvH[mi][0]), "+f"(pvH[mi][1]),
                      "+f"(pvH[mi][2]), "+f"(pvH[mi][3])
                    : "r"(*(unsigned*)&er[0]), "r"(*(unsigned*)&er[1]),
                      "r"(*(unsigned*)&er[2]), "r"(*(unsigned*)&er[3]),
                      "r"(vh0), "r"(vh1));
                asm volatile(
                    "mma.sync.aligned.m16n8k16.row.col.f32.f16.f16.f32 "
                    "{%0,%1,%2,%3}, {%4,%5,%6,%7}, {%8,%9}, {%0,%1,%2,%3};"
                    : "+f"(pvR[mi][0]), "+f"(pvR[mi][1]),
                      "+f"(pvR[mi][2]), "+f"(pvR[mi][3])
                    : "r"(*(unsigned*)&eh[0]), "r"(*(unsigned*)&eh[1]),
                      "r"(*(unsigned*)&eh[2]), "r"(*(unsigned*)&eh[3]),
                      "r"(vr0), "r"(vr1));
            }
        }
    }

    // -------- cross-warp PV merge (wn=0 stores, wn=1 adds) --------
    float* PvH = Pv;
    float* PvR = Pv + BMT * 9;
    __syncthreads();
    if (wn == 0) {
        #pragma unroll
        for (int mi = 0; mi < 2; ++mi) {
            const int r = wm * 32 + mi * 16 + g;
            PvH[r * 9 + 2 * tq]           = pvH[mi][0];
            PvH[r * 9 + 2 * tq + 1]       = pvH[mi][1];
            PvH[(r + 8) * 9 + 2 * tq]     = pvH[mi][2];
            PvH[(r + 8) * 9 + 2 * tq + 1] = pvH[mi][3];
            PvR[r * 9 + 2 * tq]           = pvR[mi][0];
            PvR[r * 9 + 2 * tq + 1]       = pvR[mi][1];
            PvR[(r + 8) * 9 + 2 * tq]     = pvR[mi][2];
            PvR[(r + 8) * 9 + 2 * tq + 1] = pvR[mi][3];
        }
    }
    __syncthreads();
    if (wn == 1) {
        #pragma unroll
        for (int mi = 0; mi < 2; ++mi) {
            const int r = wm * 32 + mi * 16 + g;
            PvH[r * 9 + 2 * tq]           += pvH[mi][0];
            PvH[r * 9 + 2 * tq + 1]       += pvH[mi][1];
            PvH[(r + 8) * 9 + 2 * tq]     += pvH[mi][2];
            PvH[(r + 8) * 9 + 2 * tq + 1] += pvH[mi][3];
            PvR[r * 9 + 2 * tq]           += pvR[mi][0];
            PvR[r * 9 + 2 * tq + 1]       += pvR[mi][1];
            PvR[(r + 8) * 9 + 2 * tq]     += pvR[mi][2];
            PvR[(r + 8) * 9 + 2 * tq + 1] += pvR[mi][3];
        }
    }
    __syncthreads();

    if (tid < BMT) {
        float* out = g_pv + (((size_t)b * MSPLIT + mh) * 6) * NN + n0 + tid;
        #pragma unroll
        for (int j = 0; j < 6; ++j)
            out[j * NN] = PvH[tid * 9 + j] + PvR[tid * 9 + j];
    }
}

// ======================= reductions =========================================
__device__ __forceinline__ float warp_sum(float v) {
    #pragma unroll
    for (int o = 16; o; o >>= 1) v += __shfl_down_sync(0xffffffffu, v, o);
    return v;
}
__device__ __forceinline__ float warp_max(float v) {
    #pragma unroll
    for (int o = 16; o; o >>= 1) v = fmaxf(v, __shfl_down_sync(0xffffffffu, v, o));
    return v;
}
__device__ __forceinline__ float warp_min(float v) {
    #pragma unroll
    for (int o = 16; o; o >>= 1) v = fminf(v, __shfl_down_sync(0xffffffffu, v, o));
    return v;
}

// ======================= finalize: merge partials, mask, H, SVD, R,t =======
// 512 threads; each thread owns exactly 4 consecutive n (float4, single shot)
// -> max MLP, no serial per-n loops.
__device__ __forceinline__ float sigm(float x) { return 1.f / (1.f + __expf(-x)); }

__global__ __launch_bounds__(512)
void finalize_kernel(const float* __restrict__ src,
                     const float* __restrict__ sdm,
                     const float* __restrict__ sim,
                     float* __restrict__ out) {
    __shared__ float scorr[5 * NN];
    __shared__ float part[16][9];
    __shared__ float bc[20];

    const int b = blockIdx.x;
    const int tid  = threadIdx.x;
    const int lane = tid & 31;
    const int w    = tid >> 5;
    const int n4   = tid * 4;        // this thread's 4 n-indices

    const float* S  = src + (size_t)b * 3 * NN;
    const float* Dm = sdm + (size_t)b * NN;
    const float* Im = sim + (size_t)b * NN;
    const float* P  = g_pv + ((size_t)b * MSPLIT * 6) * NN;

    // ---- merge the M-partials (vectorized, all loads independent) ----
    float4 sv[6];
    #pragma unroll
    for (int j = 0; j < 6; ++j) {
        float4 acc = make_float4(0.f, 0.f, 0.f, 0.f);
        #pragma unroll
        for (int mh = 0; mh < MSPLIT; ++mh) {
            float4 p = *(const float4*)&P[((size_t)mh * 6 + j) * NN + n4];
            acc.x += p.x; acc.y += p.y; acc.z += p.z; acc.w += p.w;
        }
        sv[j] = acc;
    }
    {
        float4 inv = make_float4(1.f / sv[5].x, 1.f / sv[5].y,
                                 1.f / sv[5].z, 1.f / sv[5].w);
        #pragma unroll
        for (int j = 0; j < 5; ++j) {
            float4 c = make_float4(sv[j].x * inv.x, sv[j].y * inv.y,
                                   sv[j].z * inv.z, sv[j].w * inv.w);
            *(float4*)&scorr[j * NN + n4] = c;
        }
    }
    __syncthreads();

    // ---- pass 1: means + mask min/max (vectorized) ----
    const float4 s0v = *(const float4*)&S[n4];
    const float4 s1v = *(const float4*)&S[NN + n4];
    const float4 s2v = *(const float4*)&S[2 * NN + n4];
    const float4 dmv = *(const float4*)&Dm[n4];
    const float4 imv = *(const float4*)&Im[n4];
    const float4 c0v = *(const float4*)&scorr[n4];
    const float4 c1v = *(const float4*)&scorr[NN + n4];
    const float4 c2v = *(const float4*)&scorr[2 * NN + n4];
    const float4 c3v = *(const float4*)&scorr[3 * NN + n4];
    const float4 c4v = *(const float4*)&scorr[4 * NN + n4];

    float mk[4];
    {
        const float dep[4] = {0.5f * (dmv.x + c3v.x), 0.5f * (dmv.y + c3v.y),
                              0.5f * (dmv.z + c3v.z), 0.5f * (dmv.w + c3v.w)};
        const float img[4] = {0.5f * (imv.x + c4v.x), 0.5f * (imv.y + c4v.y),
                              0.5f * (imv.z + c4v.z), 0.5f * (imv.w + c4v.w)};
        #pragma unroll
        for (int u = 0; u < 4; ++u) mk[u] = sigm(dep[u]) * sigm(img[u]);
    }

    float a[8];
    a[0] = s0v.x + s0v.y + s0v.z + s0v.w;
    a[1] = s1v.x + s1v.y + s1v.z + s1v.w;
    a[2] = s2v.x + s2v.y + s2v.z + s2v.w;
    a[3] = c0v.x + c0v.y + c0v.z + c0v.w;
    a[4] = c1v.x + c1v.y + c1v.z + c1v.w;
    a[5] = c2v.x + c2v.y + c2v.z + c2v.w;
    a[6] = fminf(fminf(mk[0], mk[1]), fminf(mk[2], mk[3]));
    a[7] = fmaxf(fmaxf(mk[0], mk[1]), fmaxf(mk[2], mk[3]));

    #pragma unroll
    for (int j = 0; j < 6; ++j) a[j] = warp_sum(a[j]);
    a[6] = warp_min(a[6]);
    a[7] = warp_max(a[7]);
    if (lane == 0)
        #pragma unroll
        for (int j = 0; j < 8; ++j) part[w][j] = a[j];
    __syncthreads();
    if (tid < 8) {
        float r = part[0][tid];
        if (tid < 6)      { for (int i = 1; i < 16; ++i) r += part[i][tid];        r *= (1.f / NN); }
        else if (tid == 6){ for (int i = 1; i < 16; ++i) r = fminf(r, part[i][6]); }
        else              { for (int i = 1; i < 16; ++i) r = fmaxf(r, part[i][7]); }
        bc[tid] = r;
    }
    __syncthreads();
    const float sm0 = bc[0], sm1 = bc[1], sm2 = bc[2];
    const float cm0 = bc[3], cm1 = bc[4], cm2 = bc[5];
    const float MN = bc[6], MX = bc[7];
    const float invden = 1.f / fmaxf(MX - MN, 1e-6f);

    // ---- pass 2: weighted covariance H (data already in registers) ----
    float h[9];
    #pragma unroll
    for (int i = 0; i < 9; ++i) h[i] = 0.f;
    {
        const float x0a[4] = {s0v.x - sm0, s0v.y - sm0, s0v.z - sm0, s0v.w - sm0};
        const float x1a[4] = {s1v.x - sm1, s1v.y - sm1, s1v.z - sm1, s1v.w - sm1};
        const float x2a[4] = {s2v.x - sm2, s2v.y - sm2, s2v.z - sm2, s2v.w - sm2};
        const float y0a[4] = {c0v.x - cm0, c0v.y - cm0, c0v.z - cm0, c0v.w - cm0};
        const float y1a[4] = {c1v.x - cm1, c1v.y - cm1, c1v.z - cm1, c1v.w - cm1};
        const float y2a[4] = {c2v.x - cm2, c2v.y - cm2, c2v.z - cm2, c2v.w - cm2};
        #pragma unroll
        for (int u = 0; u < 4; ++u) {
            const float wt = (mk[u] - MN) * invden;
            h[0] += wt * x0a[u] * y0a[u]; h[1] += wt * x0a[u] * y1a[u]; h[2] += wt * x0a[u] * y2a[u];
            h[3] += wt * x1a[u] * y0a[u]; h[4] += wt * x1a[u] * y1a[u]; h[5] += wt * x1a[u] * y2a[u];
            h[6] += wt * x2a[u] * y0a[u]; h[7] += wt * x2a[u] * y1a[u]; h[8] += wt * x2a[u] * y2a[u];
        }
    }
    #pragma unroll
    for (int i = 0; i < 9; ++i) h[i] = warp_sum(h[i]);
    __syncthreads();
    if (lane == 0)
        #pragma unroll
        for (int i = 0; i < 9; ++i) part[w][i] = h[i];
    __syncthreads();
    if (tid < 9) {
        float r = part[0][tid];
        for (int i = 1; i < 16; ++i) r += part[i][tid];
        bc[8 + tid] = r;
    }
    __syncthreads();

    if (tid == 0) {
        double Hd[3][3];
        for (int i = 0; i < 3; ++i)
            for (int j = 0; j < 3; ++j) Hd[i][j] = (double)bc[8 + i * 3 + j];

        double A[3][3];
        for (int i = 0; i < 3; ++i)
            for (int j = 0; j < 3; ++j) {
                double s = 0;
                for (int k = 0; k < 3; ++k) s += Hd[k][i] * Hd[k][j];
                A[i][j] = s;
            }
        double V[3][3] = {{1, 0, 0}, {0, 1, 0}, {0, 0, 1}};
        const int pr[3] = {0, 0, 1}, qr[3] = {1, 2, 2};
        for (int sweep = 0; sweep < 8; ++sweep) {
            for (int pi = 0; pi < 3; ++pi) {
                const int p = pr[pi], q = qr[pi];
                double apq = A[p][q];
                if (fabs(apq) < 1e-300) continue;
                double theta = (A[q][q] - A[p][p]) / (2.0 * apq);
                double t = ((theta >= 0.0) ? 1.0 : -1.0) /
                           (fabs(theta) + sqrt(1.0 + theta * theta));
                double cth = 1.0 / sqrt(1.0 + t * t);
                double sth = t * cth;
                for (int k = 0; k < 3; ++k) {
                    double akp = A[k][p], akq = A[k][q];
                    A[k][p] = cth * akp - sth * akq;
                    A[k][q] = sth * akp + cth * akq;
                }
                for (int k = 0; k < 3; ++k) {
                    double apk = A[p][k], aqk = A[q][k];
                    A[p][k] = cth * apk - sth * aqk;
                    A[q][k] = sth * apk + cth * aqk;
                }
                for (int k = 0; k < 3; ++k) {
                    double vkp = V[k][p], vkq = V[k][q];
                    V[k][p] = cth * vkp - sth * vkq;
                    V[k][q] = sth * vkp + cth * vkq;
                }
            }
        }
        double w3[3] = {A[0][0], A[1][1], A[2][2]};
        for (int i = 0; i < 2; ++i)
            for (int j = i + 1; j < 3; ++j)
                if (w3[j] > w3[i]) {
                    double tw = w3[i]; w3[i] = w3[j]; w3[j] = tw;
                    for (int k = 0; k < 3; ++k) {
                        double tv = V[k][i]; V[k][i] = V[k][j]; V[k][j] = tv;
                    }
                }
        double U[3][3];
        for (int j = 0; j < 3; ++j) {
            double sig = sqrt(w3[j] > 0.0 ? w3[j] : 0.0);
            double inv = 1.0 / (sig > 1e-30 ? sig : 1e-30);
            for (int i = 0; i < 3; ++i)
                U[i][j] = (Hd[i][0] * V[0][j] + Hd[i][1] * V[1][j] + Hd[i][2] * V[2][j]) * inv;
        }
        double R[3][3];
        for (int i = 0; i < 3; ++i)
            for (int j = 0; j < 3; ++j)
                R[i][j] = V[i][0] * U[j][0] + V[i][1] * U[j][1] + V[i][2] * U[j][2];
        double det = R[0][0] * (R[1][1] * R[2][2] - R[1][2] * R[2][1])
                   - R[0][1] * (R[1][0] * R[2][2] - R[1][2] * R[2][0])
                   + R[0][2] * (R[1][0] * R[2][1] - R[1][1] * R[2][0]);
        if (det < 0.0) {
            for (int k = 0; k < 3; ++k) V[k][2] = -V[k][2];
            for (int i = 0; i < 3; ++i)
                for (int j = 0; j < 3; ++j)
                    R[i][j] = V[i][0] * U[j][0] + V[i][1] * U[j][1] + V[i][2] * U[j][2];
        }
        const double smv[3] = {sm0, sm1, sm2};
        const double cmv[3] = {cm0, cm1, cm2};

        float* Rout = out + b * 9;
        float* tout = out + BATCH * 9 + b * 3;
        for (int i = 0; i < 3; ++i) {
            for (int j = 0; j < 3; ++j) Rout[i * 3 + j] = (float)R[i][j];
            double ti = -(R[i][0] * smv[0] + R[i][1] * smv[1] + R[i][2] * smv[2]) + cmv[i];
            tout[i] = (float)ti;
        }
    }
}

// ======================= launch ============================================
extern "C" void kernel_launch(void* const* d_in, const int* in_sizes, int n_in,
                              void* d_out, int out_size) {
    const float* src_emb = (const float*)d_in[0];
    const float* tgt_emb = (const float*)d_in[1];
    const float* src     = (const float*)d_in[2];
    const float* tgt     = (const float*)d_in[3];
    const float* sdm     = (const float*)d_in[4];
    const float* tdm     = (const float*)d_in[5];
    const float* sim     = (const float*)d_in[6];
    const float* tim     = (const float*)d_in[7];
    float* out = (float*)d_out;

    cudaFuncSetAttribute(fused_attn, cudaFuncAttributeMaxDynamicSharedMemorySize,
                         SM_TOTAL_BYTES);

    dim3 gc(NN / 32, DK / 32, 2 * BATCH);
    conv_transpose2<<<gc, 256>>>(src_emb, tgt_emb);
    dim3 gv(MM / 256, BATCH);
    prep_v<<<gv, 256>>>(tgt, tdm, tim);

    dim3 grid(NN / BMT, MSPLIT, BATCH);   // 16 x 4 x 16 = 1024 blocks
    fused_attn<<<grid, THREADS, SM_TOTAL_BYTES>>>();
    finalize_kernel<<<BATCH, 512>>>(src, sdm, sim, out);
}